// round 11
// baseline (speedup 1.0000x reference)
#include <cuda_runtime.h>
#include <cuda_bf16.h>
#include <math.h>

#define NN 2048
#define BB 32
#define NSTEPS 10
#define MROWS 16              // rows per CTA
#define CTAS 128
#define THREADS 256
#define NCHUNK 8
#define KCH 256               // B chunk columns
#define ASTR 2056             // A smem stride (bf16 elems)
#define BSTR 264              // B chunk smem stride
#define SA_ELEMS (MROWS * ASTR)
#define SBUF_ELEMS (64 * BSTR)
#define SMEM_BYTES ((SA_ELEMS + 3 * SBUF_ELEMS) * 2)

// Persistent scratch (no allocations allowed)
__device__ __align__(16) __nv_bfloat16 g_SCb[3][64 * NN];  // triple-buffered sin/cos
__device__ __align__(16) float2 g_cohP[CTAS * BB];
__device__ __align__(16) float g_theta_fallback[BB * NN];
__device__ __align__(128) unsigned g_flag[CTAS * 32];      // one 128B line per CTA
__device__ __align__(128) unsigned g_cnt;
__device__ __align__(128) unsigned g_gen;

static __device__ __forceinline__ void cp16(void* dst_smem, const void* src) {
    unsigned d = (unsigned)__cvta_generic_to_shared(dst_smem);
    asm volatile("cp.async.cg.shared.global [%0], [%1], 16;\n" :: "r"(d), "l"(src));
}
static __device__ __forceinline__ void cp_commit() {
    asm volatile("cp.async.commit_group;\n");
}
template <int N>
static __device__ __forceinline__ void cp_wait() {
    asm volatile("cp.async.wait_group %0;\n" :: "n"(N));
}

// Full-grid barrier (prologue/epilogue only).
static __device__ __forceinline__ void gbar() {
    __syncthreads();
    if (threadIdx.x == 0) {
        unsigned my;
        asm volatile("ld.acquire.gpu.global.u32 %0, [%1];"
                     : "=r"(my) : "l"(&g_gen) : "memory");
        __threadfence();
        unsigned arr = atomicAdd(&g_cnt, 1u);
        if (arr == CTAS - 1) {
            g_cnt = 0;
            asm volatile("red.release.gpu.global.add.u32 [%0], %1;"
                         :: "l"(&g_gen), "r"(1u) : "memory");
        } else {
            unsigned v;
            do {
                __nanosleep(64);
                asm volatile("ld.acquire.gpu.global.u32 %0, [%1];"
                             : "=r"(v) : "l"(&g_gen) : "memory");
            } while (v == my);
        }
        __threadfence();
    }
    __syncthreads();
}

// Per-warp collective poll: lanes 0..15 poll the 16 producer flags of chunk ch.
static __device__ __forceinline__ void pollw(int ch, unsigned target, int lane) {
    const unsigned* addr = &g_flag[(ch * 16 + (lane & 15)) * 32];
    for (;;) {
        unsigned x = target;
        if (lane < 16)
            asm volatile("ld.acquire.gpu.global.u32 %0, [%1];"
                         : "=r"(x) : "l"(addr) : "memory");
        if (__all_sync(0xffffffffu, x >= target)) break;
        __nanosleep(20);
    }
}

// CTA-level signal: stores -> fence -> bar -> single release-increment.
static __device__ __forceinline__ void signal(unsigned* flag, int tid) {
    __threadfence();
    __syncthreads();
    if (tid == 0)
        asm volatile("red.release.gpu.global.add.u32 [%0], %1;"
                     :: "l"(flag), "r"(1u) : "memory");
}

__global__ void __launch_bounds__(THREADS, 1)
k_all(const float* __restrict__ theta_in, const float* __restrict__ K,
      const float* __restrict__ omega, const float* __restrict__ Kg,
      const float* __restrict__ mu, float* __restrict__ th_out,
      float* __restrict__ coh_out) {
    extern __shared__ __align__(16) char smem_raw[];
    __nv_bfloat16* sA = (__nv_bfloat16*)smem_raw;        // resident 16x2048 K tile
    __nv_bfloat16* sBuf0 = sA + SA_ELEMS;                // 3 B-chunk buffers

    int tid  = threadIdx.x;
    int lane = tid & 31;
    int w    = tid >> 5;
    int bid  = blockIdx.x;
    int i0   = bid * MROWS;
    int g    = lane >> 2, t4 = lane & 3;

    // update mapping: (batch bb, rows irow, irow+1)
    int bb   = tid >> 3;
    int rloc = (tid & 7) * 2;
    int irow = i0 + rloc;
    int eidx = bb * NN + irow;

    // ---- prologue: reset flag, convert A tile (16 x 2048 fp32 -> bf16) ----
    if (tid == 0) g_flag[bid * 32] = 0u;
    {
        const float* Kt = K + (size_t)i0 * NN;
#pragma unroll 4
        for (int it = 0; it < 32; it++) {
            int idx = it * THREADS + tid;       // 8192 float4 (512 per row)
            int row = idx >> 9, c = idx & 511;
            float4 v = *(const float4*)(Kt + (size_t)row * NN + c * 4);
            __nv_bfloat162 lo = __floats2bfloat162_rn(v.x, v.y);
            __nv_bfloat162 hi = __floats2bfloat162_rn(v.z, v.w);
            uint2 pk = make_uint2(*(unsigned*)&lo, *(unsigned*)&hi);
            *(uint2*)(sA + row * ASTR + c * 4) = pk;
        }
    }
    float th0 = theta_in[eidx], th1 = theta_in[eidx + 1];
    float om0 = omega[irow],    om1 = omega[irow + 1];
    float coef = (Kg[0] * (1.0f / NN)) * (mu[0] * 0.5f);
    float s0, c0, s1, c1;
    sincosf(th0, &s0, &c0);    // one-time accurate seed
    sincosf(th1, &s1, &c1);
    __nv_bfloat162 sb2 = __floats2bfloat162_rn(s0, s1);
    __nv_bfloat162 cb2 = __floats2bfloat162_rn(c0, c1);
    *(__nv_bfloat162*)&g_SCb[0][eidx]           = sb2;
    *(__nv_bfloat162*)&g_SCb[0][32 * NN + eidx] = cb2;
    float si0 = __low2float(sb2), si1 = __high2float(sb2);
    float ci0 = __low2float(cb2), ci1 = __high2float(cb2);

    gbar();

    // ---- 10 steps: chunked full-K GEMM + local update, ONE sync hop/step ----
    for (int step = 0; step < NSTEPS; step++) {
        int par3 = step % 3;
        const __nv_bfloat16* Bsrc = g_SCb[par3];

        // fill helper pattern: 2048 x 16B per chunk, 8 per thread
        // prefetch chunk 0
        pollw(0, (unsigned)step, lane);
        {
            __nv_bfloat16* d = sBuf0;     // chunk 0 -> buffer 0
#pragma unroll
            for (int it = 0; it < 8; it++) {
                int idx = it * THREADS + tid;
                int row = idx >> 5, c = idx & 31;
                cp16(d + row * BSTR + c * 8,
                     Bsrc + (size_t)row * NN + c * 8);
            }
        }
        cp_commit();

        float acc0 = 0.f, acc1 = 0.f, acc2 = 0.f, acc3 = 0.f;

        for (int ch = 0; ch < NCHUNK; ch++) {
            if (ch < 7) {
                pollw(ch + 1, (unsigned)step, lane);
                __nv_bfloat16* d = sBuf0 + ((ch + 1) % 3) * SBUF_ELEMS;
                const __nv_bfloat16* s = Bsrc + (ch + 1) * KCH;
#pragma unroll
                for (int it = 0; it < 8; it++) {
                    int idx = it * THREADS + tid;
                    int row = idx >> 5, c = idx & 31;
                    cp16(d + row * BSTR + c * 8,
                         s + (size_t)row * NN + c * 8);
                }
                cp_commit();
                cp_wait<1>();
            } else {
                cp_wait<0>();
            }
            __syncthreads();

            const __nv_bfloat16* bufp = sBuf0 + (ch % 3) * SBUF_ELEMS;
            int colbase = ch * KCH;
#pragma unroll
            for (int kk = 0; kk < KCH; kk += 16) {
                unsigned a0, a1, a2, a3;
                const __nv_bfloat16* ap =
                    sA + (lane & 15) * ASTR + colbase + kk + ((lane >> 4) * 8);
                unsigned sa = (unsigned)__cvta_generic_to_shared(ap);
                asm volatile(
                    "ldmatrix.sync.aligned.m8n8.x4.shared.b16 {%0,%1,%2,%3}, [%4];"
                    : "=r"(a0), "=r"(a1), "=r"(a2), "=r"(a3) : "r"(sa));
                const __nv_bfloat16* p = bufp + (w * 8 + g) * BSTR + kk + 2 * t4;
                unsigned b0 = *(const unsigned*)p;
                unsigned b1 = *(const unsigned*)(p + 8);
                asm volatile(
                    "mma.sync.aligned.m16n8k16.row.col.f32.bf16.bf16.f32 "
                    "{%0,%1,%2,%3}, {%4,%5,%6,%7}, {%8,%9}, {%0,%1,%2,%3};"
                    : "+f"(acc0), "+f"(acc1), "+f"(acc2), "+f"(acc3)
                    : "r"(a0), "r"(a1), "r"(a2), "r"(a3), "r"(b0), "r"(b1));
            }
        }

        // exchange 16x64 fp32 results via smem (alias buffer 0)
        __syncthreads();
        float* sX = (float*)sBuf0;        // 16 rows x 65 stride
        {
            int col = w * 8 + 2 * t4;
            sX[g * 65 + col]           = acc0;
            sX[g * 65 + col + 1]       = acc1;
            sX[(g + 8) * 65 + col]     = acc2;
            sX[(g + 8) * 65 + col + 1] = acc3;
        }
        __syncthreads();

        // update (all data CTA-local)
        float Ks0 = sX[rloc * 65 + bb],       Kc0 = sX[rloc * 65 + 32 + bb];
        float Ks1 = sX[(rloc + 1) * 65 + bb], Kc1 = sX[(rloc + 1) * 65 + 32 + bb];
        th0 = fmaf(0.1f, om0 + coef * (ci0 * Ks0 - si0 * Kc0), th0);
        th1 = fmaf(0.1f, om1 + coef * (ci1 * Ks1 - si1 * Kc1), th1);

        if (step < NSTEPS - 1) {
            int wpar = (step + 1) % 3;
            __sincosf(th0, &s0, &c0);   // bf16 rounding dominates intrinsic err
            __sincosf(th1, &s1, &c1);
            sb2 = __floats2bfloat162_rn(s0, s1);
            cb2 = __floats2bfloat162_rn(c0, c1);
            *(__nv_bfloat162*)&g_SCb[wpar][eidx]           = sb2;
            *(__nv_bfloat162*)&g_SCb[wpar][32 * NN + eidx] = cb2;
            si0 = __low2float(sb2); si1 = __high2float(sb2);
            ci0 = __low2float(cb2); ci1 = __high2float(cb2);
            signal(&g_flag[bid * 32], tid);   // ONE hop per step
        }
    }

    // ---- epilogue: reference-exact wrap (once), output, coherence ----
    float sn0, cn0, sn1, cn1;
    sincosf(th0, &sn0, &cn0); th0 = atan2f(sn0, cn0);
    sincosf(th1, &sn1, &cn1); th1 = atan2f(sn1, cn1);
    th_out[eidx]     = th0;
    th_out[eidx + 1] = th1;

    if (coh_out) {
        sincosf(th0, &sn0, &cn0);       // trig of wrapped theta (as reference)
        sincosf(th1, &sn1, &cn1);
        float ssP = sn0 + sn1, ccP = cn0 + cn1;
#pragma unroll
        for (int o = 4; o > 0; o >>= 1) {   // reduce 8-lane groups (same batch)
            ssP += __shfl_xor_sync(0xffffffffu, ssP, o);
            ccP += __shfl_xor_sync(0xffffffffu, ccP, o);
        }
        if ((lane & 7) == 0)
            g_cohP[bid * BB + bb] = make_float2(ssP, ccP);
        gbar();
        if (bid < BB) {       // CTA b reduces batch b over 128 CTA partials
            float* rs = (float*)smem_raw;
            float* rc = rs + THREADS;
            float ss = 0.f, cc = 0.f;
            if (tid < CTAS) {
                float2 p = g_cohP[tid * BB + bid];
                ss = p.x; cc = p.y;
            }
            rs[tid] = ss; rc[tid] = cc;
            __syncthreads();
            for (int o = 128; o > 0; o >>= 1) {
                if (tid < o) { rs[tid] += rs[tid + o]; rc[tid] += rc[tid + o]; }
                __syncthreads();
            }
            if (tid == 0) {
                float sm = rs[0] * (1.0f / NN), cm = rc[0] * (1.0f / NN);
                coh_out[bid] = sqrtf(cm * cm + sm * sm);
            }
        }
    }
}

extern "C" void kernel_launch(void* const* d_in, const int* in_sizes, int n_in,
                              void* d_out, int out_size) {
    const float* theta = (const float*)d_in[0];
    const float* K     = (const float*)d_in[1];
    const float* omega = (const float*)d_in[2];
    const float* Kg    = (const float*)d_in[3];
    const float* mu    = (const float*)d_in[4];
    float* out = (float*)d_out;

    float* th_buf;
    float* coh_out = nullptr;
    if (out_size >= BB * NN) {
        th_buf = out;
        if (out_size >= BB * NN + BB) coh_out = out + BB * NN;
    } else {
        float* sym;
        cudaGetSymbolAddress((void**)&sym, g_theta_fallback);
        th_buf = sym;
        coh_out = out;
    }

    cudaFuncSetAttribute(k_all, cudaFuncAttributeMaxDynamicSharedMemorySize,
                         SMEM_BYTES);
    k_all<<<CTAS, THREADS, SMEM_BYTES>>>(theta, K, omega, Kg, mu,
                                         th_buf, coh_out);
}

// round 12
// speedup vs baseline: 1.6035x; 1.6035x over previous
#include <cuda_runtime.h>
#include <cuda_bf16.h>
#include <math.h>

#define NN 2048
#define BB 32
#define NSTEPS 10
#define KSPLIT 8
#define KC 256                // K chunk per CTA
#define MT 128                // rows per CTA (MMA tile)
#define CTAS 128
#define THREADS 256
#define SSTR 264              // smem row stride (bf16 elems)
#define SA_ELEMS (MT * SSTR)
#define SB_ELEMS (64 * SSTR)
#define SMEM_BYTES ((SA_ELEMS + SB_ELEMS) * 2)

// Persistent scratch (no allocations allowed)
__device__ __align__(16) __nv_bfloat16 g_SCb[3][64 * NN];  // triple-buffered sin/cos
__device__ __align__(16) float g_ps[2][KSPLIT][BB * NN];   // partials K*sin [col][row]
__device__ __align__(16) float g_pc[2][KSPLIT][BB * NN];   // partials K*cos
__device__ __align__(16) float2 g_cohP[CTAS * BB];
__device__ __align__(16) float g_theta_fallback[BB * NN];
// flagP: per-warp producer flags [ib][producer ks][warp w]
__device__ __align__(128) unsigned g_flagP[16 * 64];
// flagU: per-warp update flags [ib][ks][warp w] (warp w owns batches 4w..4w+3)
__device__ __align__(128) unsigned g_flagU[16 * 64];
// global barrier (prologue/epilogue only)
__device__ __align__(128) unsigned g_cnt;
__device__ __align__(128) unsigned g_gen;

static __device__ __forceinline__ void cp16(void* dst_smem, const void* src) {
    unsigned d = (unsigned)__cvta_generic_to_shared(dst_smem);
    asm volatile("cp.async.cg.shared.global [%0], [%1], 16;\n" :: "r"(d), "l"(src));
}
static __device__ __forceinline__ void cp_commit() {
    asm volatile("cp.async.commit_group;\n");
}
template <int N>
static __device__ __forceinline__ void cp_wait() {
    asm volatile("cp.async.wait_group %0;\n" :: "n"(N));
}

// Full-grid barrier (prologue/epilogue only).
static __device__ __forceinline__ void gbar() {
    __syncthreads();
    if (threadIdx.x == 0) {
        unsigned my;
        asm volatile("ld.acquire.gpu.global.u32 %0, [%1];"
                     : "=r"(my) : "l"(&g_gen) : "memory");
        __threadfence();
        unsigned arr = atomicAdd(&g_cnt, 1u);
        if (arr == CTAS - 1) {
            g_cnt = 0;
            asm volatile("red.release.gpu.global.add.u32 [%0], %1;"
                         :: "l"(&g_gen), "r"(1u) : "memory");
        } else {
            unsigned v;
            do {
                __nanosleep(64);
                asm volatile("ld.acquire.gpu.global.u32 %0, [%1];"
                             : "=r"(v) : "l"(&g_gen) : "memory");
            } while (v == my);
        }
        __threadfence();
    }
    __syncthreads();
}

// Warp-collective poll: lanes with `need` poll *addr until >= target.
static __device__ __forceinline__ void poll_ge(const unsigned* addr,
                                               unsigned target, bool need) {
    for (;;) {
        unsigned x = target;
        if (need)
            asm volatile("ld.acquire.gpu.global.u32 %0, [%1];"
                         : "=r"(x) : "l"(addr) : "memory");
        if (__all_sync(0xffffffffu, x >= target)) break;
        __nanosleep(20);
    }
}

// Warp-level signal: this warp's stores -> syncwarp -> lane0 release-inc.
static __device__ __forceinline__ void signal_warp(unsigned* flag, int lane) {
    __syncwarp();
    if (lane == 0)
        asm volatile("red.release.gpu.global.add.u32 [%0], %1;"
                     :: "l"(flag), "r"(1u) : "memory");
}

__global__ void __launch_bounds__(THREADS, 1)
k_all(const float* __restrict__ theta_in, const float* __restrict__ K,
      const float* __restrict__ omega, const float* __restrict__ Kg,
      const float* __restrict__ mu, float* __restrict__ th_out,
      float* __restrict__ coh_out) {
    extern __shared__ __align__(16) char smem_raw[];
    __nv_bfloat16* sA = (__nv_bfloat16*)smem_raw;        // resident K tile
    __nv_bfloat16* sB = sA + SA_ELEMS;                   // per-step sin/cos tile

    int tid  = threadIdx.x;
    int lane = tid & 31;
    int w    = tid >> 5;
    int bid  = blockIdx.x;
    int ib   = bid >> 3, ks = bid & 7;
    int i0   = ib * MT, k0 = ks * KC;
    int g    = lane >> 2, t4 = lane & 3;

    // update-slice mapping: this CTA updates rows [i0 + 16*ks, +16) x 32 batches
    int bb   = tid >> 3;                       // batch 0..31 (warp w: 4w..4w+3)
    int rloc = (tid & 7) * 2;                  // local row pair
    int irow = i0 + ks * 16 + rloc;
    int eidx = bb * NN + irow;

    // ---- prologue: reset flags, convert K tile, seed state ----
    if (tid < 8) {
        g_flagP[ib * 64 + ks * 8 + tid] = 0u;
        g_flagU[ib * 64 + ks * 8 + tid] = 0u;
    }
    {
        const float* Kt = K + (size_t)i0 * NN + k0;
#pragma unroll 4
        for (int it = 0; it < 32; it++) {
            int idx = it * THREADS + tid;           // 8192 float4
            int row = idx >> 6, c = idx & 63;
            float4 v = *(const float4*)(Kt + (size_t)row * NN + c * 4);
            __nv_bfloat162 lo = __floats2bfloat162_rn(v.x, v.y);
            __nv_bfloat162 hi = __floats2bfloat162_rn(v.z, v.w);
            uint2 pk = make_uint2(*(unsigned*)&lo, *(unsigned*)&hi);
            *(uint2*)(sA + row * SSTR + c * 4) = pk;
        }
    }
    float th0 = theta_in[eidx], th1 = theta_in[eidx + 1];
    float om0 = omega[irow],    om1 = omega[irow + 1];
    float coef = (Kg[0] * (1.0f / NN)) * (mu[0] * 0.5f);
    float s0, c0, s1, c1;
    sincosf(th0, &s0, &c0);    // one-time accurate seed
    sincosf(th1, &s1, &c1);
    __nv_bfloat162 sb2 = __floats2bfloat162_rn(s0, s1);
    __nv_bfloat162 cb2 = __floats2bfloat162_rn(c0, c1);
    *(__nv_bfloat162*)&g_SCb[0][eidx]           = sb2;
    *(__nv_bfloat162*)&g_SCb[0][32 * NN + eidx] = cb2;
    float si0 = __low2float(sb2), si1 = __high2float(sb2);
    float ci0 = __low2float(cb2), ci1 = __high2float(cb2);

    gbar();

    // ---- 10 steps ----
    for (int step = 0; step < NSTEPS; step++) {
        int par  = step & 1;        // partials parity
        int par3 = step % 3;        // g_SCb read buffer
        const __nv_bfloat16* Bsrc = g_SCb[par3];

        // Per-warp pipelined hopU: warp w handles batch-group w.
        // Poll the 16 producer warps (row-groups 2ks, 2ks+1, warp w), then
        // fill B rows {4w..4w+3} (sin) and {32+4w..32+4w+3} (cos).
        {
            const unsigned* a = (lane < 8)
                ? &g_flagU[(2 * ks) * 64 + lane * 8 + w]
                : &g_flagU[(2 * ks + 1) * 64 + (lane - 8) * 8 + w];
            poll_ge(a, (unsigned)step, lane < 16);   // step 0: trivially true
#pragma unroll
            for (int it = 0; it < 8; it++) {
                int row = (it < 4) ? (4 * w + it) : (32 + 4 * w + (it - 4));
                cp16(sB + row * SSTR + lane * 8,
                     Bsrc + (size_t)row * NN + k0 + lane * 8);
            }
            cp_commit();
            cp_wait<0>();
        }
        __syncthreads();

        float acc[8][4];
#pragma unroll
        for (int nt = 0; nt < 8; nt++)
#pragma unroll
            for (int r = 0; r < 4; r++) acc[nt][r] = 0.f;

#pragma unroll 4
        for (int kk = 0; kk < KC; kk += 16) {
            unsigned a0, a1, a2, a3;
            const __nv_bfloat16* ap =
                sA + (w * 16 + (lane & 15)) * SSTR + kk + ((lane >> 4) * 8);
            unsigned sa = (unsigned)__cvta_generic_to_shared(ap);
            asm volatile(
                "ldmatrix.sync.aligned.m8n8.x4.shared.b16 {%0,%1,%2,%3}, [%4];"
                : "=r"(a0), "=r"(a1), "=r"(a2), "=r"(a3) : "r"(sa));
#pragma unroll
            for (int nt = 0; nt < 8; nt++) {
                const __nv_bfloat16* p = sB + (nt * 8 + g) * SSTR + kk + 2 * t4;
                unsigned b0 = *(const unsigned*)p;
                unsigned b1 = *(const unsigned*)(p + 8);
                asm volatile(
                    "mma.sync.aligned.m16n8k16.row.col.f32.bf16.bf16.f32 "
                    "{%0,%1,%2,%3}, {%4,%5,%6,%7}, {%8,%9}, {%0,%1,%2,%3};"
                    : "+f"(acc[nt][0]), "+f"(acc[nt][1]),
                      "+f"(acc[nt][2]), "+f"(acc[nt][3])
                    : "r"(a0), "r"(a1), "r"(a2), "r"(a3), "r"(b0), "r"(b1));
            }
        }

        // store partials (cols 0-31 sin, 32-63 cos), [col][row] layout;
        // each warp signals its per-warp flagP immediately after its stores.
        {
            int ir = i0 + w * 16 + g;
#pragma unroll
            for (int nt = 0; nt < 8; nt++) {
                int col = nt * 8 + 2 * t4;
                float* dst = (nt < 4) ? g_ps[par][ks] : g_pc[par][ks];
                int cb = col & 31;
                dst[(size_t)cb * NN + ir]           = acc[nt][0];
                dst[(size_t)(cb + 1) * NN + ir]     = acc[nt][1];
                dst[(size_t)cb * NN + ir + 8]       = acc[nt][2];
                dst[(size_t)(cb + 1) * NN + ir + 8] = acc[nt][3];
            }
        }
        signal_warp(&g_flagP[ib * 64 + ks * 8 + w], lane);   // -> step+1

        // wait for warp-ks tiles of the 8 producer CTAs (group ib)
        if (w == 0) {
            const unsigned* a = &g_flagP[ib * 64 + (lane & 7) * 8 + ks];
            poll_ge(a, (unsigned)(step + 1), lane < 8);
        }
        __syncthreads();

        // update: reduce split-K partials, integrate
        float ss0 = 0.f, ss1 = 0.f, cs0 = 0.f, cs1 = 0.f;
#pragma unroll
        for (int kq = 0; kq < KSPLIT; kq++) {
            float2 p = *(const float2*)&g_ps[par][kq][eidx];
            ss0 += p.x; ss1 += p.y;
            float2 q = *(const float2*)&g_pc[par][kq][eidx];
            cs0 += q.x; cs1 += q.y;
        }
        th0 = fmaf(0.1f, om0 + coef * (ci0 * ss0 - si0 * cs0), th0);
        th1 = fmaf(0.1f, om1 + coef * (ci1 * ss1 - si1 * cs1), th1);

        if (step < NSTEPS - 1) {
            int wpar = (step + 1) % 3;
            __sincosf(th0, &s0, &c0);   // bf16 rounding dominates intrinsic err
            __sincosf(th1, &s1, &c1);
            sb2 = __floats2bfloat162_rn(s0, s1);
            cb2 = __floats2bfloat162_rn(c0, c1);
            *(__nv_bfloat162*)&g_SCb[wpar][eidx]           = sb2;
            *(__nv_bfloat162*)&g_SCb[wpar][32 * NN + eidx] = cb2;
            // per-warp flagU: warp w owns batches 4w..4w+3 for our 16 rows
            signal_warp(&g_flagU[ib * 64 + ks * 8 + w], lane);  // -> step+1
            si0 = __low2float(sb2); si1 = __high2float(sb2);
            ci0 = __low2float(cb2); ci1 = __high2float(cb2);
        }
    }

    // ---- epilogue: reference-exact wrap (once), output, coherence ----
    float sn0, cn0, sn1, cn1;
    sincosf(th0, &sn0, &cn0); th0 = atan2f(sn0, cn0);
    sincosf(th1, &sn1, &cn1); th1 = atan2f(sn1, cn1);
    th_out[eidx]     = th0;
    th_out[eidx + 1] = th1;

    if (coh_out) {
        sincosf(th0, &sn0, &cn0);       // trig of wrapped theta (as reference)
        sincosf(th1, &sn1, &cn1);
        float ssP = sn0 + sn1, ccP = cn0 + cn1;
#pragma unroll
        for (int o = 4; o > 0; o >>= 1) {   // reduce 8-lane groups (same batch)
            ssP += __shfl_xor_sync(0xffffffffu, ssP, o);
            ccP += __shfl_xor_sync(0xffffffffu, ccP, o);
        }
        if ((lane & 7) == 0)
            g_cohP[bid * BB + bb] = make_float2(ssP, ccP);
        gbar();
        if (bid < BB) {       // CTA b reduces batch b over 128 CTA partials
            float* rs = (float*)smem_raw;
            float* rc = rs + THREADS;
            float ss = 0.f, cc = 0.f;
            if (tid < CTAS) {
                float2 p = g_cohP[tid * BB + bid];
                ss = p.x; cc = p.y;
            }
            rs[tid] = ss; rc[tid] = cc;
            __syncthreads();
            for (int o = 128; o > 0; o >>= 1) {
                if (tid < o) { rs[tid] += rs[tid + o]; rc[tid] += rc[tid + o]; }
                __syncthreads();
            }
            if (tid == 0) {
                float sm = rs[0] * (1.0f / NN), cm = rc[0] * (1.0f / NN);
                coh_out[bid] = sqrtf(cm * cm + sm * sm);
            }
        }
    }
}

extern "C" void kernel_launch(void* const* d_in, const int* in_sizes, int n_in,
                              void* d_out, int out_size) {
    const float* theta = (const float*)d_in[0];
    const float* K     = (const float*)d_in[1];
    const float* omega = (const float*)d_in[2];
    const float* Kg    = (const float*)d_in[3];
    const float* mu    = (const float*)d_in[4];
    float* out = (float*)d_out;

    float* th_buf;
    float* coh_out = nullptr;
    if (out_size >= BB * NN) {
        th_buf = out;
        if (out_size >= BB * NN + BB) coh_out = out + BB * NN;
    } else {
        float* sym;
        cudaGetSymbolAddress((void**)&sym, g_theta_fallback);
        th_buf = sym;
        coh_out = out;
    }

    cudaFuncSetAttribute(k_all, cudaFuncAttributeMaxDynamicSharedMemorySize,
                         SMEM_BYTES);
    k_all<<<CTAS, THREADS, SMEM_BYTES>>>(theta, K, omega, Kg, mu,
                                         th_buf, coh_out);
}

// round 13
// speedup vs baseline: 1.6184x; 1.0093x over previous
#include <cuda_runtime.h>
#include <cuda_bf16.h>
#include <math.h>

#define NN 2048
#define BB 32
#define NSTEPS 10
#define KSPLIT 8
#define KC 256                // K chunk per CTA
#define MT 128                // rows per CTA (MMA tile)
#define CTAS 128
#define THREADS 256
#define SSTR 264              // smem row stride (bf16 elems)
#define SA_ELEMS (MT * SSTR)
#define SB_ELEMS (64 * SSTR)
#define SMEM_BYTES ((SA_ELEMS + SB_ELEMS) * 2)

// Persistent scratch (no allocations allowed)
__device__ __align__(16) __nv_bfloat16 g_SCb[3][64 * NN];  // triple-buffered sin/cos
__device__ __align__(16) float g_ps[2][KSPLIT][BB * NN];   // partials K*sin [col][row]
__device__ __align__(16) float g_pc[2][KSPLIT][BB * NN];   // partials K*cos
__device__ __align__(16) float2 g_cohP[CTAS * BB];
__device__ __align__(16) float g_theta_fallback[BB * NN];
// flagP: per-warp producer flags [ib][producer ks][warp w]
__device__ __align__(128) unsigned g_flagP[16 * 64];
// flagU: per-warp update flags [ib][ks][warp w] (warp w owns batches 4w..4w+3)
__device__ __align__(128) unsigned g_flagU[16 * 64];
// global barrier (prologue/epilogue only)
__device__ __align__(128) unsigned g_cnt;
__device__ __align__(128) unsigned g_gen;

static __device__ __forceinline__ void cp16(void* dst_smem, const void* src) {
    unsigned d = (unsigned)__cvta_generic_to_shared(dst_smem);
    asm volatile("cp.async.cg.shared.global [%0], [%1], 16;\n" :: "r"(d), "l"(src));
}
static __device__ __forceinline__ void cp_commit() {
    asm volatile("cp.async.commit_group;\n");
}
template <int N>
static __device__ __forceinline__ void cp_wait() {
    asm volatile("cp.async.wait_group %0;\n" :: "n"(N));
}

// Full-grid barrier (prologue/epilogue only).
static __device__ __forceinline__ void gbar() {
    __syncthreads();
    if (threadIdx.x == 0) {
        unsigned my;
        asm volatile("ld.acquire.gpu.global.u32 %0, [%1];"
                     : "=r"(my) : "l"(&g_gen) : "memory");
        __threadfence();
        unsigned arr = atomicAdd(&g_cnt, 1u);
        if (arr == CTAS - 1) {
            g_cnt = 0;
            asm volatile("red.release.gpu.global.add.u32 [%0], %1;"
                         :: "l"(&g_gen), "r"(1u) : "memory");
        } else {
            unsigned v;
            do {
                __nanosleep(64);
                asm volatile("ld.acquire.gpu.global.u32 %0, [%1];"
                             : "=r"(v) : "l"(&g_gen) : "memory");
            } while (v == my);
        }
        __threadfence();
    }
    __syncthreads();
}

// Warp-collective poll: lanes with `need` poll *addr until >= target.
static __device__ __forceinline__ void poll_ge(const unsigned* addr,
                                               unsigned target, bool need) {
    for (;;) {
        unsigned x = target;
        if (need)
            asm volatile("ld.acquire.gpu.global.u32 %0, [%1];"
                         : "=r"(x) : "l"(addr) : "memory");
        if (__all_sync(0xffffffffu, x >= target)) break;
        __nanosleep(20);
    }
}

// Warp-level signal: this warp's stores -> syncwarp -> lane0 release-inc.
static __device__ __forceinline__ void signal_warp(unsigned* flag, int lane) {
    __syncwarp();
    if (lane == 0)
        asm volatile("red.release.gpu.global.add.u32 [%0], %1;"
                     :: "l"(flag), "r"(1u) : "memory");
}

__global__ void __launch_bounds__(THREADS, 1)
k_all(const float* __restrict__ theta_in, const float* __restrict__ K,
      const float* __restrict__ omega, const float* __restrict__ Kg,
      const float* __restrict__ mu, float* __restrict__ th_out,
      float* __restrict__ coh_out) {
    extern __shared__ __align__(16) char smem_raw[];
    __nv_bfloat16* sA = (__nv_bfloat16*)smem_raw;        // resident K tile
    __nv_bfloat16* sB = sA + SA_ELEMS;                   // per-step sin/cos tile

    int tid  = threadIdx.x;
    int lane = tid & 31;
    int w    = tid >> 5;
    int bid  = blockIdx.x;
    int ib   = bid >> 3, ks = bid & 7;
    int i0   = ib * MT, k0 = ks * KC;
    int g    = lane >> 2, t4 = lane & 3;

    // update-slice mapping: this CTA updates rows [i0 + 16*ks, +16) x 32 batches
    int bb   = tid >> 3;                       // batch 0..31 (warp w: 4w..4w+3)
    int rloc = (tid & 7) * 2;                  // local row pair
    int irow = i0 + ks * 16 + rloc;
    int eidx = bb * NN + irow;

    // ---- prologue: reset flags, convert K tile, seed state ----
    if (tid < 8) {
        g_flagP[ib * 64 + ks * 8 + tid] = 0u;
        g_flagU[ib * 64 + ks * 8 + tid] = 0u;
    }
    {
        const float* Kt = K + (size_t)i0 * NN + k0;
#pragma unroll 4
        for (int it = 0; it < 32; it++) {
            int idx = it * THREADS + tid;           // 8192 float4
            int row = idx >> 6, c = idx & 63;
            float4 v = *(const float4*)(Kt + (size_t)row * NN + c * 4);
            __nv_bfloat162 lo = __floats2bfloat162_rn(v.x, v.y);
            __nv_bfloat162 hi = __floats2bfloat162_rn(v.z, v.w);
            uint2 pk = make_uint2(*(unsigned*)&lo, *(unsigned*)&hi);
            *(uint2*)(sA + row * SSTR + c * 4) = pk;
        }
    }
    float th0 = theta_in[eidx], th1 = theta_in[eidx + 1];
    float om0 = omega[irow],    om1 = omega[irow + 1];
    float coef = (Kg[0] * (1.0f / NN)) * (mu[0] * 0.5f);
    float s0, c0, s1, c1;
    sincosf(th0, &s0, &c0);    // one-time accurate seed
    sincosf(th1, &s1, &c1);
    __nv_bfloat162 sb2 = __floats2bfloat162_rn(s0, s1);
    __nv_bfloat162 cb2 = __floats2bfloat162_rn(c0, c1);
    *(__nv_bfloat162*)&g_SCb[0][eidx]           = sb2;
    *(__nv_bfloat162*)&g_SCb[0][32 * NN + eidx] = cb2;
    float si0 = __low2float(sb2), si1 = __high2float(sb2);
    float ci0 = __low2float(cb2), ci1 = __high2float(cb2);

    gbar();

    // ---- 10 steps ----
    for (int step = 0; step < NSTEPS; step++) {
        int par  = step & 1;        // partials parity
        int par3 = step % 3;        // g_SCb read buffer
        const __nv_bfloat16* Bsrc = g_SCb[par3];

        // Per-warp pipelined hopU: warp w handles batch-group w.
        {
            const unsigned* a = (lane < 8)
                ? &g_flagU[(2 * ks) * 64 + lane * 8 + w]
                : &g_flagU[(2 * ks + 1) * 64 + (lane - 8) * 8 + w];
            poll_ge(a, (unsigned)step, lane < 16);   // step 0: trivially true
#pragma unroll
            for (int it = 0; it < 8; it++) {
                int row = (it < 4) ? (4 * w + it) : (32 + 4 * w + (it - 4));
                cp16(sB + row * SSTR + lane * 8,
                     Bsrc + (size_t)row * NN + k0 + lane * 8);
            }
            cp_commit();
            cp_wait<0>();
        }
        __syncthreads();

        float acc[8][4];
#pragma unroll
        for (int nt = 0; nt < 8; nt++)
#pragma unroll
            for (int r = 0; r < 4; r++) acc[nt][r] = 0.f;

        // B-fragment ldmatrix lane mapping (per nt-pair):
        //   nt = ntp*2 + (lane>>4); khalf = (lane>>3)&1; row-in-tile = lane&7
        int b_nt_off = (lane >> 4);          // 0 or 1
        int b_khalf  = ((lane >> 3) & 1) * 8;
        int b_rowin  = lane & 7;

#pragma unroll 4
        for (int kk = 0; kk < KC; kk += 16) {
            unsigned a0, a1, a2, a3;
            const __nv_bfloat16* ap =
                sA + (w * 16 + (lane & 15)) * SSTR + kk + ((lane >> 4) * 8);
            unsigned sa = (unsigned)__cvta_generic_to_shared(ap);
            asm volatile(
                "ldmatrix.sync.aligned.m8n8.x4.shared.b16 {%0,%1,%2,%3}, [%4];"
                : "=r"(a0), "=r"(a1), "=r"(a2), "=r"(a3) : "r"(sa));
#pragma unroll
            for (int ntp = 0; ntp < 4; ntp++) {
                // one x4 ldmatrix = b0/b1 fragments for nt = 2*ntp and 2*ntp+1
                int nt0 = 2 * ntp;
                const __nv_bfloat16* bp =
                    sB + ((nt0 + b_nt_off) * 8 + b_rowin) * SSTR + kk + b_khalf;
                unsigned sb_ = (unsigned)__cvta_generic_to_shared(bp);
                unsigned b0, b1, b2, b3;
                asm volatile(
                    "ldmatrix.sync.aligned.m8n8.x4.shared.b16 {%0,%1,%2,%3}, [%4];"
                    : "=r"(b0), "=r"(b1), "=r"(b2), "=r"(b3) : "r"(sb_));
                asm volatile(
                    "mma.sync.aligned.m16n8k16.row.col.f32.bf16.bf16.f32 "
                    "{%0,%1,%2,%3}, {%4,%5,%6,%7}, {%8,%9}, {%0,%1,%2,%3};"
                    : "+f"(acc[nt0][0]), "+f"(acc[nt0][1]),
                      "+f"(acc[nt0][2]), "+f"(acc[nt0][3])
                    : "r"(a0), "r"(a1), "r"(a2), "r"(a3), "r"(b0), "r"(b1));
                asm volatile(
                    "mma.sync.aligned.m16n8k16.row.col.f32.bf16.bf16.f32 "
                    "{%0,%1,%2,%3}, {%4,%5,%6,%7}, {%8,%9}, {%0,%1,%2,%3};"
                    : "+f"(acc[nt0 + 1][0]), "+f"(acc[nt0 + 1][1]),
                      "+f"(acc[nt0 + 1][2]), "+f"(acc[nt0 + 1][3])
                    : "r"(a0), "r"(a1), "r"(a2), "r"(a3), "r"(b2), "r"(b3));
            }
        }

        // store partials (cols 0-31 sin, 32-63 cos), [col][row] layout;
        // each warp signals its per-warp flagP immediately after its stores.
        {
            int ir = i0 + w * 16 + g;
#pragma unroll
            for (int nt = 0; nt < 8; nt++) {
                int col = nt * 8 + 2 * t4;
                float* dst = (nt < 4) ? g_ps[par][ks] : g_pc[par][ks];
                int cb = col & 31;
                dst[(size_t)cb * NN + ir]           = acc[nt][0];
                dst[(size_t)(cb + 1) * NN + ir]     = acc[nt][1];
                dst[(size_t)cb * NN + ir + 8]       = acc[nt][2];
                dst[(size_t)(cb + 1) * NN + ir + 8] = acc[nt][3];
            }
        }
        signal_warp(&g_flagP[ib * 64 + ks * 8 + w], lane);   // -> step+1

        // wait for warp-ks tiles of the 8 producer CTAs (group ib)
        if (w == 0) {
            const unsigned* a = &g_flagP[ib * 64 + (lane & 7) * 8 + ks];
            poll_ge(a, (unsigned)(step + 1), lane < 8);
        }
        __syncthreads();

        // update: reduce split-K partials, integrate
        float ss0 = 0.f, ss1 = 0.f, cs0 = 0.f, cs1 = 0.f;
#pragma unroll
        for (int kq = 0; kq < KSPLIT; kq++) {
            float2 p = *(const float2*)&g_ps[par][kq][eidx];
            ss0 += p.x; ss1 += p.y;
            float2 q = *(const float2*)&g_pc[par][kq][eidx];
            cs0 += q.x; cs1 += q.y;
        }
        th0 = fmaf(0.1f, om0 + coef * (ci0 * ss0 - si0 * cs0), th0);
        th1 = fmaf(0.1f, om1 + coef * (ci1 * ss1 - si1 * cs1), th1);

        if (step < NSTEPS - 1) {
            int wpar = (step + 1) % 3;
            __sincosf(th0, &s0, &c0);   // bf16 rounding dominates intrinsic err
            __sincosf(th1, &s1, &c1);
            sb2 = __floats2bfloat162_rn(s0, s1);
            cb2 = __floats2bfloat162_rn(c0, c1);
            *(__nv_bfloat162*)&g_SCb[wpar][eidx]           = sb2;
            *(__nv_bfloat162*)&g_SCb[wpar][32 * NN + eidx] = cb2;
            // per-warp flagU: warp w owns batches 4w..4w+3 for our 16 rows
            signal_warp(&g_flagU[ib * 64 + ks * 8 + w], lane);  // -> step+1
            si0 = __low2float(sb2); si1 = __high2float(sb2);
            ci0 = __low2float(cb2); ci1 = __high2float(cb2);
        }
    }

    // ---- epilogue: reference-exact wrap (once), output, coherence ----
    float sn0, cn0, sn1, cn1;
    sincosf(th0, &sn0, &cn0); th0 = atan2f(sn0, cn0);
    sincosf(th1, &sn1, &cn1); th1 = atan2f(sn1, cn1);
    th_out[eidx]     = th0;
    th_out[eidx + 1] = th1;

    if (coh_out) {
        sincosf(th0, &sn0, &cn0);       // trig of wrapped theta (as reference)
        sincosf(th1, &sn1, &cn1);
        float ssP = sn0 + sn1, ccP = cn0 + cn1;
#pragma unroll
        for (int o = 4; o > 0; o >>= 1) {   // reduce 8-lane groups (same batch)
            ssP += __shfl_xor_sync(0xffffffffu, ssP, o);
            ccP += __shfl_xor_sync(0xffffffffu, ccP, o);
        }
        if ((lane & 7) == 0)
            g_cohP[bid * BB + bb] = make_float2(ssP, ccP);
        gbar();
        if (bid < BB) {       // CTA b reduces batch b over 128 CTA partials
            float* rs = (float*)smem_raw;
            float* rc = rs + THREADS;
            float ss = 0.f, cc = 0.f;
            if (tid < CTAS) {
                float2 p = g_cohP[tid * BB + bid];
                ss = p.x; cc = p.y;
            }
            rs[tid] = ss; rc[tid] = cc;
            __syncthreads();
            for (int o = 128; o > 0; o >>= 1) {
                if (tid < o) { rs[tid] += rs[tid + o]; rc[tid] += rc[tid + o]; }
                __syncthreads();
            }
            if (tid == 0) {
                float sm = rs[0] * (1.0f / NN), cm = rc[0] * (1.0f / NN);
                coh_out[bid] = sqrtf(cm * cm + sm * sm);
            }
        }
    }
}

extern "C" void kernel_launch(void* const* d_in, const int* in_sizes, int n_in,
                              void* d_out, int out_size) {
    const float* theta = (const float*)d_in[0];
    const float* K     = (const float*)d_in[1];
    const float* omega = (const float*)d_in[2];
    const float* Kg    = (const float*)d_in[3];
    const float* mu    = (const float*)d_in[4];
    float* out = (float*)d_out;

    float* th_buf;
    float* coh_out = nullptr;
    if (out_size >= BB * NN) {
        th_buf = out;
        if (out_size >= BB * NN + BB) coh_out = out + BB * NN;
    } else {
        float* sym;
        cudaGetSymbolAddress((void**)&sym, g_theta_fallback);
        th_buf = sym;
        coh_out = out;
    }

    cudaFuncSetAttribute(k_all, cudaFuncAttributeMaxDynamicSharedMemorySize,
                         SMEM_BYTES);
    k_all<<<CTAS, THREADS, SMEM_BYTES>>>(theta, K, omega, Kg, mu,
                                         th_buf, coh_out);
}